// round 7
// baseline (speedup 1.0000x reference)
#include <cuda_runtime.h>
#include <cuda_bf16.h>
#include <math.h>
#include <stdint.h>

#define EMB 1024
#define DHEAD 64
#define BATCH 8
#define SEQ 2048
#define MTOT (BATCH * SEQ)   // 16384
#define NSPLIT 4

// ---------------------------------------------------------------------------
// Scratch (__device__ globals; no cudaMalloc allowed)
// ---------------------------------------------------------------------------
__device__ __nv_bfloat16 g_Qh[MTOT * DHEAD], g_Ql[MTOT * DHEAD]; // pre-scaled 0.125*log2e
__device__ __nv_bfloat16 g_Kh[MTOT * DHEAD], g_Kl[MTOT * DHEAD];
__device__ __nv_bfloat16 g_Uh[MTOT * DHEAD], g_Ul[MTOT * DHEAD]; // U = x@w_v1
__device__ __nv_bfloat16 g_Oh[MTOT * DHEAD], g_Ol[MTOT * DHEAD]; // attn out (pre w_v2)
__device__ __nv_bfloat16 g_Wh[3 * EMB * DHEAD], g_Wl[3 * EMB * DHEAD]; // wq|wk|wv1
__device__ __nv_bfloat16 g_W2h[DHEAD * EMB], g_W2l[DHEAD * EMB];
// split-KV partials (unnormalized)
__device__ float g_Op[NSPLIT][MTOT * DHEAD];
__device__ float g_l[NSPLIT][MTOT];

// ---------------------------------------------------------------------------
// Helpers
// ---------------------------------------------------------------------------
__device__ __forceinline__ uint32_t smem_u32(const void* p) {
    uint32_t a;
    asm("{ .reg .u64 t; cvta.to.shared.u64 t, %1; cvt.u32.u64 %0, t; }" : "=r"(a) : "l"(p));
    return a;
}
__device__ __forceinline__ void ldsm4(uint32_t* r, uint32_t a) {
    asm volatile("ldmatrix.sync.aligned.m8n8.x4.shared.b16 {%0,%1,%2,%3}, [%4];"
                 : "=r"(r[0]), "=r"(r[1]), "=r"(r[2]), "=r"(r[3]) : "r"(a));
}
__device__ __forceinline__ void ldsm4t(uint32_t* r, uint32_t a) {
    asm volatile("ldmatrix.sync.aligned.m8n8.x4.trans.shared.b16 {%0,%1,%2,%3}, [%4];"
                 : "=r"(r[0]), "=r"(r[1]), "=r"(r[2]), "=r"(r[3]) : "r"(a));
}
__device__ __forceinline__ void mma_bf16(float* c, const uint32_t* a, uint32_t b0, uint32_t b1) {
    asm volatile("mma.sync.aligned.m16n8k16.row.col.f32.bf16.bf16.f32 "
                 "{%0,%1,%2,%3}, {%4,%5,%6,%7}, {%8,%9}, {%0,%1,%2,%3};"
                 : "+f"(c[0]), "+f"(c[1]), "+f"(c[2]), "+f"(c[3])
                 : "r"(a[0]), "r"(a[1]), "r"(a[2]), "r"(a[3]), "r"(b0), "r"(b1));
}
__device__ __forceinline__ uint32_t packbf(float v0, float v1) {
    uint32_t r;
    asm("cvt.rn.bf16x2.f32 %0, %1, %2;" : "=r"(r) : "f"(v1), "f"(v0));
    return r;
}
__device__ __forceinline__ void split2(float v0, float v1, uint32_t& hi, uint32_t& lo) {
    hi = packbf(v0, v1);
    float h0 = __uint_as_float(hi << 16);
    float h1 = __uint_as_float(hi & 0xFFFF0000u);
    lo = packbf(v0 - h0, v1 - h1);
}
__device__ __forceinline__ float ex2(float x) {
    float r;
    asm("ex2.approx.ftz.f32 %0, %1;" : "=f"(r) : "f"(x));
    return r;
}
__device__ __forceinline__ void cp16(uint32_t s, const void* g) {
    asm volatile("cp.async.cg.shared.global [%0], [%1], 16;" :: "r"(s), "l"(g));
}
#define CP_COMMIT() asm volatile("cp.async.commit_group;" ::: "memory")
#define CP_WAIT1()  asm volatile("cp.async.wait_group 1;" ::: "memory")

// ---------------------------------------------------------------------------
// Kernel 0: convert weights to bf16 hi/lo
// ---------------------------------------------------------------------------
__global__ __launch_bounds__(256) void convw_kernel(
    const float* __restrict__ wq, const float* __restrict__ wk,
    const float* __restrict__ wv1, const float* __restrict__ wv2)
{
    int p = (blockIdx.x * 256 + threadIdx.x) * 2;
    float v0, v1;
    __nv_bfloat16 *dh, *dl;
    int off;
    if (p < 3 * EMB * DHEAD) {
        const float* src = (p < EMB * DHEAD) ? wq : (p < 2 * EMB * DHEAD) ? wk : wv1;
        int e = p & (EMB * DHEAD - 1);
        v0 = src[e]; v1 = src[e + 1];
        dh = g_Wh; dl = g_Wl; off = p;
    } else {
        int e = p - 3 * EMB * DHEAD;
        v0 = wv2[e]; v1 = wv2[e + 1];
        dh = g_W2h; dl = g_W2l; off = e;
    }
    uint32_t hi, lo;
    split2(v0, v1, hi, lo);
    *reinterpret_cast<uint32_t*>(dh + off) = hi;
    *reinterpret_cast<uint32_t*>(dl + off) = lo;
}

// ---------------------------------------------------------------------------
// Kernel 1: fused projections via mma.sync. 64-row tiles, 128 threads,
// grid = 256 blocks. Weights cp.async double-buffered; x reg-pipelined.
// ---------------------------------------------------------------------------
#define PJ_XPITCH 80
#define PJ_WPITCH 144
#define PJ_XH 0
#define PJ_XL (64 * PJ_XPITCH)            // 5120
#define PJ_WBASE (2 * 64 * PJ_XPITCH)     // 10240
#define PJ_WTILE (32 * PJ_WPITCH)         // 4608
#define PJ_WSET (3 * PJ_WTILE)            // 13824
#define PJ_WBUF (2 * PJ_WSET)             // 27648
#define PJ_SMEM (PJ_WBASE + 2 * PJ_WBUF)  // 65536

__global__ __launch_bounds__(128) void proj_kernel(const float* __restrict__ x)
{
    extern __shared__ char sm[];
    const uint32_t sb = smem_u32(sm);
    const int tid = threadIdx.x, w = tid >> 5, lane = tid & 31;
    const int gr = lane >> 2, tig = lane & 3;
    const int m0 = blockIdx.x * 64;

    float acc[3][8][4];
#pragma unroll
    for (int t = 0; t < 3; t++)
#pragma unroll
        for (int j = 0; j < 8; j++)
#pragma unroll
            for (int q = 0; q < 4; q++) acc[t][j][q] = 0.f;

    const int mrow = w * 16 + (lane & 7) + ((lane >> 3) & 1) * 8;
    const int akb = (lane >> 4) * 16;
    const int krow = (lane >> 4) * 16 + ((lane >> 3) & 1) * 8 + (lane & 7);

    auto wload = [&](int k0, uint32_t bufbase) {
#pragma unroll
        for (int i = tid; i < 768; i += 128) {
            int t = i >> 8, r = (i >> 3) & 31, c = i & 7;
            size_t gi = (size_t)t * EMB * 64 + (size_t)(k0 + r) * 64 + c * 8;
            uint32_t d = bufbase + t * PJ_WTILE + r * PJ_WPITCH + c * 16;
            cp16(sb + d, g_Wh + gi);
            cp16(sb + d + PJ_WSET, g_Wl + gi);
        }
    };

    float4 xv[4], xn[4];
#pragma unroll
    for (int j = 0; j < 4; j++) {
        int i = tid + j * 128, r = i >> 3, c = (i & 7) * 4;
        xv[j] = *reinterpret_cast<const float4*>(&x[(size_t)(m0 + r) * EMB + c]);
    }
    wload(0, PJ_WBASE);
    CP_COMMIT();

    for (int it = 0; it < 32; it++) {
        const int k0 = it * 32;
        const uint32_t wb = PJ_WBASE + (uint32_t)(it & 1) * PJ_WBUF;
        if (it < 31) wload(k0 + 32, PJ_WBASE + (uint32_t)((it + 1) & 1) * PJ_WBUF);
        CP_COMMIT();
        if (it < 31) {
#pragma unroll
            for (int j = 0; j < 4; j++) {
                int i = tid + j * 128, r = i >> 3, c = (i & 7) * 4;
                xn[j] = *reinterpret_cast<const float4*>(&x[(size_t)(m0 + r) * EMB + k0 + 32 + c]);
            }
        }
#pragma unroll
        for (int j = 0; j < 4; j++) {
            int i = tid + j * 128, r = i >> 3, c = (i & 7) * 4;
            uint32_t h0, l0, h1, l1;
            split2(xv[j].x, xv[j].y, h0, l0);
            split2(xv[j].z, xv[j].w, h1, l1);
            uint32_t* ph = reinterpret_cast<uint32_t*>(sm + PJ_XH + r * PJ_XPITCH + c * 2);
            ph[0] = h0; ph[1] = h1;
            uint32_t* pl = reinterpret_cast<uint32_t*>(sm + PJ_XL + r * PJ_XPITCH + c * 2);
            pl[0] = l0; pl[1] = l1;
        }
        CP_WAIT1();
        __syncthreads();

        uint32_t ah[2][4], al[2][4];
#pragma unroll
        for (int kk = 0; kk < 2; kk++) {
            ldsm4(ah[kk], sb + PJ_XH + mrow * PJ_XPITCH + kk * 32 + akb);
            ldsm4(al[kk], sb + PJ_XL + mrow * PJ_XPITCH + kk * 32 + akb);
        }
#pragma unroll
        for (int t = 0; t < 3; t++) {
#pragma unroll
            for (int j = 0; j < 8; j++) {
                uint32_t bh[4], bl[4];
                ldsm4t(bh, sb + wb + t * PJ_WTILE + krow * PJ_WPITCH + j * 16);
                ldsm4t(bl, sb + wb + PJ_WSET + t * PJ_WTILE + krow * PJ_WPITCH + j * 16);
                float* c = acc[t][j];
                mma_bf16(c, ah[0], bh[0], bh[1]);
                mma_bf16(c, ah[1], bh[2], bh[3]);
                mma_bf16(c, ah[0], bl[0], bl[1]);
                mma_bf16(c, ah[1], bl[2], bl[3]);
                mma_bf16(c, al[0], bh[0], bh[1]);
                mma_bf16(c, al[1], bh[2], bh[3]);
            }
        }
        __syncthreads();
#pragma unroll
        for (int j = 0; j < 4; j++) xv[j] = xn[j];
    }

#pragma unroll
    for (int t = 0; t < 3; t++) {
        __nv_bfloat16* dh = (t == 0) ? g_Qh : (t == 1) ? g_Kh : g_Uh;
        __nv_bfloat16* dl = (t == 0) ? g_Ql : (t == 1) ? g_Kl : g_Ul;
        const float scl = (t == 0) ? 0.18033688f : 1.0f;  // 0.125 * log2(e)
#pragma unroll
        for (int j = 0; j < 8; j++) {
            int col = j * 8 + tig * 2;
            size_t r0 = (size_t)(m0 + w * 16 + gr);
            uint32_t h, l;
            split2(acc[t][j][0] * scl, acc[t][j][1] * scl, h, l);
            *reinterpret_cast<uint32_t*>(dh + r0 * 64 + col) = h;
            *reinterpret_cast<uint32_t*>(dl + r0 * 64 + col) = l;
            split2(acc[t][j][2] * scl, acc[t][j][3] * scl, h, l);
            *reinterpret_cast<uint32_t*>(dh + (r0 + 8) * 64 + col) = h;
            *reinterpret_cast<uint32_t*>(dl + (r0 + 8) * 64 + col) = l;
        }
    }
}

// ---------------------------------------------------------------------------
// Kernel 2: FA2 flash attention. 128-row q-tile, 4 warps, M=32 per warp.
// grid (SEQ/128, BATCH, NSPLIT); 128 threads. kt tiles of 64 kv rows.
// S processed in two 32-col halves to bound registers.
// ---------------------------------------------------------------------------
#define FL_PITCH 144
#define FL_TILE (64 * FL_PITCH)       // 9216
#define FL_STAGE (4 * FL_TILE)        // 36864 (KH,KL,UH,UL)
#define FL_SMEM (2 * FL_STAGE)        // 73728

__global__ __launch_bounds__(128) void flash_kernel()
{
    extern __shared__ char sm[];
    const uint32_t sb = smem_u32(sm);
    const int tid = threadIdx.x, w = tid >> 5, lane = tid & 31;
    const int gr = lane >> 2, tig = lane & 3;
    const int qt = blockIdx.x, b = blockIdx.y, par = blockIdx.z;
    const int q0 = qt * 128;
    const size_t base = (size_t)b * SEQ;
    const int ktmax = 2 * qt + 1;   // last kv tile index

    float* Op = g_Op[par];
    float* lp = g_l[par];

    if (par > ktmax) {
        // no KV tiles for this split: zero partials (rows w*32 .. w*32+31)
        float2 z = make_float2(0.f, 0.f);
#pragma unroll
        for (int m = 0; m < 2; m++) {
            size_t r0s = base + q0 + w * 32 + m * 16 + gr;
            if (tig == 0) { lp[r0s] = 0.f; lp[r0s + 8] = 0.f; }
#pragma unroll
            for (int j = 0; j < 8; j++) {
                int col = j * 8 + tig * 2;
                *reinterpret_cast<float2*>(&Op[r0s * 64 + col]) = z;
                *reinterpret_cast<float2*>(&Op[(r0s + 8) * 64 + col]) = z;
            }
        }
        return;
    }

    // stage Q (128x64 hi/lo): Qh -> stage0 bytes [0, 18432), Ql -> [18432, 36864)
    for (int i = tid; i < 128 * 8; i += 128) {
        int r = i >> 3, c = i & 7;
        size_t gq = (base + q0 + r) * 64 + c * 8;
        uint32_t d = r * FL_PITCH + c * 16;
        *reinterpret_cast<uint4*>(sm + d) = *reinterpret_cast<const uint4*>(g_Qh + gq);
        *reinterpret_cast<uint4*>(sm + 2 * FL_TILE + d) =
            *reinterpret_cast<const uint4*>(g_Ql + gq);
    }
    __syncthreads();
    uint32_t qh[2][4][4], ql[2][4][4];
    {
        const int akb = (lane >> 4) * 16;
#pragma unroll
        for (int m = 0; m < 2; m++) {
            const int mrow = w * 32 + m * 16 + (lane & 7) + ((lane >> 3) & 1) * 8;
#pragma unroll
            for (int kk = 0; kk < 4; kk++) {
                ldsm4(qh[m][kk], sb + mrow * FL_PITCH + kk * 32 + akb);
                ldsm4(ql[m][kk], sb + 2 * FL_TILE + mrow * FL_PITCH + kk * 32 + akb);
            }
        }
    }
    __syncthreads();

    auto load_tile = [&](int kt, uint32_t bb) {
        const int k0 = kt * 64;
#pragma unroll
        for (int i = tid; i < 64 * 8; i += 128) {
            int r = i >> 3, c = i & 7;
            uint32_t d = bb + r * FL_PITCH + c * 16;
            size_t gk = (base + k0 + r) * 64 + c * 8;
            cp16(sb + d, g_Kh + gk);
            cp16(sb + d + FL_TILE, g_Kl + gk);
            cp16(sb + d + 2 * FL_TILE, g_Uh + gk);
            cp16(sb + d + 3 * FL_TILE, g_Ul + gk);
        }
    };

    float o[2][8][4];
#pragma unroll
    for (int m = 0; m < 2; m++)
#pragma unroll
        for (int j = 0; j < 8; j++)
#pragma unroll
            for (int q = 0; q < 4; q++) o[m][j][q] = 0.f;
    float lsum[2][2] = {{0.f, 0.f}, {0.f, 0.f}};  // [m][row-half]

    const int wrow0 = q0 + w * 32;   // warp's min q row

    load_tile(par, 0);
    CP_COMMIT();

    int it = 0;
    for (int kt = par; kt <= ktmax; kt += NSPLIT, it++) {
        const int k0 = kt * 64;
        const uint32_t bb = (uint32_t)(it & 1) * FL_STAGE;
        if (kt + NSPLIT <= ktmax) load_tile(kt + NSPLIT, (uint32_t)((it + 1) & 1) * FL_STAGE);
        CP_COMMIT();
        CP_WAIT1();
        __syncthreads();

        const bool domask = (k0 + 63 > wrow0);

#pragma unroll
        for (int h = 0; h < 2; h++) {   // 32-col half of the kv tile
            // S half = Q K^T (split-bf16, 3 passes)
            float s[2][4][4];
#pragma unroll
            for (int m = 0; m < 2; m++)
#pragma unroll
                for (int j = 0; j < 4; j++)
#pragma unroll
                    for (int q = 0; q < 4; q++) s[m][j][q] = 0.f;

#pragma unroll
            for (int j = 0; j < 4; j++) {
                const int gj = h * 4 + j;
                uint32_t a0 = sb + bb + (gj * 8 + (lane & 7)) * FL_PITCH + (lane >> 3) * 16;
                uint32_t a1 = a0 + FL_TILE;
                uint32_t bh[4], bh2[4], bl[4], bl2[4];
                ldsm4(bh, a0); ldsm4(bh2, a0 + 64);
                ldsm4(bl, a1); ldsm4(bl2, a1 + 64);
#pragma unroll
                for (int m = 0; m < 2; m++) {
                    float* c = s[m][j];
                    mma_bf16(c, qh[m][0], bh[0], bh[1]);
                    mma_bf16(c, qh[m][1], bh[2], bh[3]);
                    mma_bf16(c, qh[m][2], bh2[0], bh2[1]);
                    mma_bf16(c, qh[m][3], bh2[2], bh2[3]);
                    mma_bf16(c, qh[m][0], bl[0], bl[1]);
                    mma_bf16(c, qh[m][1], bl[2], bl[3]);
                    mma_bf16(c, qh[m][2], bl2[0], bl2[1]);
                    mma_bf16(c, qh[m][3], bl2[2], bl2[3]);
                    mma_bf16(c, ql[m][0], bh[0], bh[1]);
                    mma_bf16(c, ql[m][1], bh[2], bh[3]);
                    mma_bf16(c, ql[m][2], bh2[0], bh2[1]);
                    mma_bf16(c, ql[m][3], bh2[2], bh2[3]);
                }
            }

            // softmax: p = exp2(s); mask when tile can cross diagonal
#pragma unroll
            for (int m = 0; m < 2; m++) {
                const int row0 = wrow0 + m * 16 + gr, row1 = row0 + 8;
#pragma unroll
                for (int j = 0; j < 4; j++) {
                    int cb = k0 + (h * 4 + j) * 8 + tig * 2;
                    float p0 = ex2(s[m][j][0]), p1 = ex2(s[m][j][1]);
                    float p2 = ex2(s[m][j][2]), p3 = ex2(s[m][j][3]);
                    if (domask) {
                        if (cb > row0) p0 = 0.f;
                        if (cb + 1 > row0) p1 = 0.f;
                        if (cb > row1) p2 = 0.f;
                        if (cb + 1 > row1) p3 = 0.f;
                    }
                    s[m][j][0] = p0; s[m][j][1] = p1;
                    s[m][j][2] = p2; s[m][j][3] = p3;
                    lsum[m][0] += p0 + p1;
                    lsum[m][1] += p2 + p3;
                }
            }

            // P fragments for this half (local kk = 0,1 -> global 2h, 2h+1)
            uint32_t ph[2][2][4], pl[2][2][4];
#pragma unroll
            for (int m = 0; m < 2; m++)
#pragma unroll
                for (int l = 0; l < 2; l++) {
                    split2(s[m][2 * l][0], s[m][2 * l][1], ph[m][l][0], pl[m][l][0]);
                    split2(s[m][2 * l][2], s[m][2 * l][3], ph[m][l][1], pl[m][l][1]);
                    split2(s[m][2 * l + 1][0], s[m][2 * l + 1][1], ph[m][l][2], pl[m][l][2]);
                    split2(s[m][2 * l + 1][2], s[m][2 * l + 1][3], ph[m][l][3], pl[m][l][3]);
                }

            // O += P_half @ U_half (U rows 32h..32h+31)
#pragma unroll
            for (int l = 0; l < 2; l++) {
                int krow = (2 * h + l) * 16 + ((lane >> 3) & 1) * 8 + (lane & 7);
#pragma unroll
                for (int jp = 0; jp < 4; jp++) {
                    int nbyte = (jp * 2 + (lane >> 4)) * 16;
                    uint32_t bh[4], bl[4];
                    ldsm4t(bh, sb + bb + 2 * FL_TILE + krow * FL_PITCH + nbyte);
                    ldsm4t(bl, sb + bb + 3 * FL_TILE + krow * FL_PITCH + nbyte);
#pragma unroll
                    for (int m = 0; m < 2; m++) {
                        mma_bf16(o[m][2 * jp], ph[m][l], bh[0], bh[1]);
                        mma_bf16(o[m][2 * jp + 1], ph[m][l], bh[2], bh[3]);
                        mma_bf16(o[m][2 * jp], ph[m][l], bl[0], bl[1]);
                        mma_bf16(o[m][2 * jp + 1], ph[m][l], bl[2], bl[3]);
                        mma_bf16(o[m][2 * jp], pl[m][l], bh[0], bh[1]);
                        mma_bf16(o[m][2 * jp + 1], pl[m][l], bh[2], bh[3]);
                    }
                }
            }
        }
        __syncthreads();
    }

    // reduce row sums across the 4-lane quad, write partials
#pragma unroll
    for (int m = 0; m < 2; m++) {
        float l0 = lsum[m][0], l1 = lsum[m][1];
        l0 += __shfl_xor_sync(0xffffffffu, l0, 1);
        l0 += __shfl_xor_sync(0xffffffffu, l0, 2);
        l1 += __shfl_xor_sync(0xffffffffu, l1, 1);
        l1 += __shfl_xor_sync(0xffffffffu, l1, 2);
        size_t r0s = base + q0 + w * 32 + m * 16 + gr;
        if (tig == 0) { lp[r0s] = l0; lp[r0s + 8] = l1; }
#pragma unroll
        for (int j = 0; j < 8; j++) {
            int col = j * 8 + tig * 2;
            *reinterpret_cast<float2*>(&Op[r0s * 64 + col]) =
                make_float2(o[m][j][0], o[m][j][1]);
            *reinterpret_cast<float2*>(&Op[(r0s + 8) * 64 + col]) =
                make_float2(o[m][j][2], o[m][j][3]);
        }
    }
}

// ---------------------------------------------------------------------------
// Kernel 2b: combine split-KV partials (float4/thread), normalize, emit hi/lo.
// ---------------------------------------------------------------------------
__global__ __launch_bounds__(256) void combine_kernel()
{
    int i = (blockIdx.x * 256 + threadIdx.x) * 4;
    int row = i >> 6;
    float lsum = g_l[0][row] + g_l[1][row] + g_l[2][row] + g_l[3][row];
    float inv = 1.0f / lsum;
    float4 a = *reinterpret_cast<const float4*>(&g_Op[0][i]);
    float4 b = *reinterpret_cast<const float4*>(&g_Op[1][i]);
    float4 c = *reinterpret_cast<const float4*>(&g_Op[2][i]);
    float4 d = *reinterpret_cast<const float4*>(&g_Op[3][i]);
    float v0 = (a.x + b.x + c.x + d.x) * inv;
    float v1 = (a.y + b.y + c.y + d.y) * inv;
    float v2 = (a.z + b.z + c.z + d.z) * inv;
    float v3 = (a.w + b.w + c.w + d.w) * inv;
    uint32_t h0, l0, h1, l1;
    split2(v0, v1, h0, l0);
    split2(v2, v3, h1, l1);
    *reinterpret_cast<uint2*>(g_Oh + i) = make_uint2(h0, h1);
    *reinterpret_cast<uint2*>(g_Ol + i) = make_uint2(l0, l1);
}

// ---------------------------------------------------------------------------
// Kernel 3: out[256 rows x 256 cols] = O64 @ w_v2. A staged once (bf16 hi/lo),
// W processed in two 128-col halves through one buffer. grid (4, 64).
// ---------------------------------------------------------------------------
#define OP_OPITCH 144
#define OP_WPITCH 272
#define OP_AH 0
#define OP_AL (256 * OP_OPITCH)            // 36864
#define OP_WH (2 * 256 * OP_OPITCH)        // 73728
#define OP_WL (OP_WH + 64 * OP_WPITCH)     // 91136
#define OP_SMEM (OP_WL + 64 * OP_WPITCH)   // 108544

__global__ __launch_bounds__(256) void outproj_kernel(float* __restrict__ out)
{
    extern __shared__ char sm[];
    const uint32_t sb = smem_u32(sm);
    const int tid = threadIdx.x, w = tid >> 5, lane = tid & 31;
    const int gr = lane >> 2, tig = lane & 3;
    const int row0 = blockIdx.y * 256, cbase = blockIdx.x * 256;

    for (int i = tid; i < 256 * 8; i += 256) {
        int r = i >> 3, c = i & 7;
        size_t gi = (size_t)(row0 + r) * 64 + c * 8;
        *reinterpret_cast<uint4*>(sm + OP_AH + r * OP_OPITCH + c * 16) =
            *reinterpret_cast<const uint4*>(g_Oh + gi);
        *reinterpret_cast<uint4*>(sm + OP_AL + r * OP_OPITCH + c * 16) =
            *reinterpret_cast<const uint4*>(g_Ol + gi);
    }
    for (int i = tid; i < 64 * 16; i += 256) {
        int r = i >> 4, c = i & 15;
        size_t gi = (size_t)r * EMB + cbase + c * 8;
        *reinterpret_cast<uint4*>(sm + OP_WH + r * OP_WPITCH + c * 16) =
            *reinterpret_cast<const uint4*>(g_W2h + gi);
        *reinterpret_cast<uint4*>(sm + OP_WL + r * OP_WPITCH + c * 16) =
            *reinterpret_cast<const uint4*>(g_W2l + gi);
    }
    __syncthreads();

    uint32_t ah[2][4][4], al[2][4][4];
    const int akb = (lane >> 4) * 16;
#pragma unroll
    for (int m = 0; m < 2; m++) {
        const int mrow = w * 32 + m * 16 + (lane & 7) + ((lane >> 3) & 1) * 8;
#pragma unroll
        for (int kk = 0; kk < 4; kk++) {
            ldsm4(ah[m][kk], sb + OP_AH + mrow * OP_OPITCH + kk * 32 + akb);
            ldsm4(al[m][kk], sb + OP_AL + mrow * OP_OPITCH + kk * 32 + akb);
        }
    }

#pragma unroll
    for (int h = 0; h < 2; h++) {
        if (h == 1) {
            __syncthreads();
            for (int i = tid; i < 64 * 16; i += 256) {
                int r = i >> 4, c = i & 15;
                size_t gi = (size_t)r * EMB + cbase + 128 + c * 8;
                *reinterpret_cast<uint4*>(sm + OP_WH + r * OP_WPITCH + c * 16) =
                    *reinterpret_cast<const uint4*>(g_W2h + gi);
                *reinterpret_cast<uint4*>(sm + OP_WL + r * OP_WPITCH + c * 16) =
                    *reinterpret_cast<const uint4*>(g_W2l + gi);
            }
            __syncthreads();
        }
        const int col0 = cbase + h * 128;
#pragma unroll
        for (int j = 0; j < 16; j++) {
            float c[2][4];
#pragma unroll
            for (int m = 0; m < 2; m++)
#pragma unroll
                for (int q = 0; q < 4; q++) c[m][q] = 0.f;
#pragma unroll
            for (int kp = 0; kp < 2; kp++) {
                int krow = kp * 32 + (lane >> 4) * 16 + ((lane >> 3) & 1) * 8 + (lane & 7);
                uint32_t bh[4], bl[4];
                ldsm4t(bh, sb + OP_WH + krow * OP_WPITCH + j * 16);
                ldsm4t(bl, sb + OP_WL + krow * OP_WPITCH + j * 16);
#pragma unroll
                for (int m = 0; m < 2; m++) {
                    mma_bf16(c[m], ah[m][2 * kp], bh[0], bh[1]);
                    mma_bf16(c[m], ah[m][2 * kp + 1], bh[2], bh[3]);
                    mma_bf16(c[m], ah[m][2 * kp], bl[0], bl[1]);
                    mma_bf16(c[m], ah[m][2 * kp + 1], bl[2], bl[3]);
                    mma_bf16(c[m], al[m][2 * kp], bh[0], bh[1]);
                    mma_bf16(c[m], al[m][2 * kp + 1], bh[2], bh[3]);
                }
            }
            int col = col0 + j * 8 + tig * 2;
#pragma unroll
            for (int m = 0; m < 2; m++) {
                int r = row0 + w * 32 + m * 16 + gr;
                *reinterpret_cast<float2*>(&out[(size_t)r * EMB + col]) =
                    make_float2(c[m][0], c[m][1]);
                *reinterpret_cast<float2*>(&out[(size_t)(r + 8) * EMB + col]) =
                    make_float2(c[m][2], c[m][3]);
            }
        }
    }
}

// ---------------------------------------------------------------------------
extern "C" void kernel_launch(void* const* d_in, const int* in_sizes, int n_in,
                              void* d_out, int out_size)
{
    const float* x    = (const float*)d_in[0];
    const float* w_q  = (const float*)d_in[1];
    const float* w_k  = (const float*)d_in[2];
    const float* w_v1 = (const float*)d_in[3];
    const float* w_v2 = (const float*)d_in[4];
    float* out = (float*)d_out;
    (void)in_sizes; (void)n_in; (void)out_size;

    cudaFuncSetAttribute(proj_kernel, cudaFuncAttributeMaxDynamicSharedMemorySize, PJ_SMEM);
    cudaFuncSetAttribute(flash_kernel, cudaFuncAttributeMaxDynamicSharedMemorySize, FL_SMEM);
    cudaFuncSetAttribute(outproj_kernel, cudaFuncAttributeMaxDynamicSharedMemorySize, OP_SMEM);

    convw_kernel<<<512, 256>>>(w_q, w_k, w_v1, w_v2);
    proj_kernel<<<MTOT / 64, 128, PJ_SMEM>>>(x);
    flash_kernel<<<dim3(SEQ / 128, BATCH, NSPLIT), 128, FL_SMEM>>>();
    combine_kernel<<<MTOT * DHEAD / 1024, 256>>>();
    outproj_kernel<<<dim3(EMB / 256, MTOT / 256), 256, OP_SMEM>>>(out);
}

// round 8
// speedup vs baseline: 1.0796x; 1.0796x over previous
#include <cuda_runtime.h>
#include <cuda_bf16.h>
#include <cuda_fp16.h>
#include <math.h>
#include <stdint.h>

#define EMB 1024
#define DHEAD 64
#define BATCH 8
#define SEQ 2048
#define MTOT (BATCH * SEQ)   // 16384
#define NSPLIT 4

#define LOSCALE 2048.0f
#define INV_LOSCALE 4.8828125e-4f

// ---------------------------------------------------------------------------
// Scratch (__device__ globals; no cudaMalloc allowed)
// ---------------------------------------------------------------------------
__device__ __half g_Qh[MTOT * DHEAD], g_Ql[MTOT * DHEAD]; // pre-scaled 0.125*log2e; lo x2048
__device__ __half g_Kh[MTOT * DHEAD], g_Kl[MTOT * DHEAD];
__device__ __nv_bfloat16 g_Uh[MTOT * DHEAD], g_Ul[MTOT * DHEAD]; // U bf16 (PV stays bf16)
__device__ __half g_Oh[MTOT * DHEAD], g_Ol[MTOT * DHEAD]; // attn out (pre w_v2)
__device__ __half g_Wh[3 * EMB * DHEAD], g_Wl[3 * EMB * DHEAD]; // wq|wk|wv1
__device__ __half g_W2h[DHEAD * EMB], g_W2l[DHEAD * EMB];
// split-KV partials (unnormalized)
__device__ float g_Op[NSPLIT][MTOT * DHEAD];
__device__ float g_l[NSPLIT][MTOT];

// ---------------------------------------------------------------------------
// Helpers
// ---------------------------------------------------------------------------
__device__ __forceinline__ uint32_t smem_u32(const void* p) {
    uint32_t a;
    asm("{ .reg .u64 t; cvta.to.shared.u64 t, %1; cvt.u32.u64 %0, t; }" : "=r"(a) : "l"(p));
    return a;
}
__device__ __forceinline__ void ldsm4(uint32_t* r, uint32_t a) {
    asm volatile("ldmatrix.sync.aligned.m8n8.x4.shared.b16 {%0,%1,%2,%3}, [%4];"
                 : "=r"(r[0]), "=r"(r[1]), "=r"(r[2]), "=r"(r[3]) : "r"(a));
}
__device__ __forceinline__ void ldsm4t(uint32_t* r, uint32_t a) {
    asm volatile("ldmatrix.sync.aligned.m8n8.x4.trans.shared.b16 {%0,%1,%2,%3}, [%4];"
                 : "=r"(r[0]), "=r"(r[1]), "=r"(r[2]), "=r"(r[3]) : "r"(a));
}
// bf16 x bf16 -> f32 accum
__device__ __forceinline__ void mma_bf16(float* c, const uint32_t* a, uint32_t b0, uint32_t b1) {
    asm volatile("mma.sync.aligned.m16n8k16.row.col.f32.bf16.bf16.f32 "
                 "{%0,%1,%2,%3}, {%4,%5,%6,%7}, {%8,%9}, {%0,%1,%2,%3};"
                 : "+f"(c[0]), "+f"(c[1]), "+f"(c[2]), "+f"(c[3])
                 : "r"(a[0]), "r"(a[1]), "r"(a[2]), "r"(a[3]), "r"(b0), "r"(b1));
}
// f16 x f16 -> f32 accum (hi pass)
__device__ __forceinline__ void mma_f16f32(float* c, const uint32_t* a, uint32_t b0, uint32_t b1) {
    asm volatile("mma.sync.aligned.m16n8k16.row.col.f32.f16.f16.f32 "
                 "{%0,%1,%2,%3}, {%4,%5,%6,%7}, {%8,%9}, {%0,%1,%2,%3};"
                 : "+f"(c[0]), "+f"(c[1]), "+f"(c[2]), "+f"(c[3])
                 : "r"(a[0]), "r"(a[1]), "r"(a[2]), "r"(a[3]), "r"(b0), "r"(b1));
}
// f16 x f16 -> f16 accum (cross passes, 2x rate)
__device__ __forceinline__ void mma_f16f16(uint32_t* c, const uint32_t* a, uint32_t b0, uint32_t b1) {
    asm volatile("mma.sync.aligned.m16n8k16.row.col.f16.f16.f16.f16 "
                 "{%0,%1}, {%2,%3,%4,%5}, {%6,%7}, {%0,%1};"
                 : "+r"(c[0]), "+r"(c[1])
                 : "r"(a[0]), "r"(a[1]), "r"(a[2]), "r"(a[3]), "r"(b0), "r"(b1));
}
__device__ __forceinline__ uint32_t packbf(float v0, float v1) {
    uint32_t r;
    asm("cvt.rn.bf16x2.f32 %0, %1, %2;" : "=r"(r) : "f"(v1), "f"(v0));
    return r;
}
__device__ __forceinline__ void split2(float v0, float v1, uint32_t& hi, uint32_t& lo) {
    hi = packbf(v0, v1);
    float h0 = __uint_as_float(hi << 16);
    float h1 = __uint_as_float(hi & 0xFFFF0000u);
    lo = packbf(v0 - h0, v1 - h1);
}
__device__ __forceinline__ uint32_t packh(float v0, float v1) {
    uint32_t r;
    asm("cvt.rn.f16x2.f32 %0, %1, %2;" : "=r"(r) : "f"(v1), "f"(v0));
    return r;
}
// fp16 split: hi = rn(v); lo = (v - hi) * 2048 (power-of-2, exact)
__device__ __forceinline__ void split2h(float v0, float v1, uint32_t& hi, uint32_t& lo) {
    hi = packh(v0, v1);
    __half2 h = *reinterpret_cast<__half2*>(&hi);
    float h0 = __half2float(h.x), h1 = __half2float(h.y);
    lo = packh((v0 - h0) * LOSCALE, (v1 - h1) * LOSCALE);
}
__device__ __forceinline__ float2 h2f2(uint32_t u) {
    __half2 h = *reinterpret_cast<__half2*>(&u);
    return __half22float2(h);
}
__device__ __forceinline__ float ex2(float x) {
    float r;
    asm("ex2.approx.ftz.f32 %0, %1;" : "=f"(r) : "f"(x));
    return r;
}
__device__ __forceinline__ void cp16(uint32_t s, const void* g) {
    asm volatile("cp.async.cg.shared.global [%0], [%1], 16;" :: "r"(s), "l"(g));
}
#define CP_COMMIT() asm volatile("cp.async.commit_group;" ::: "memory")
#define CP_WAIT1()  asm volatile("cp.async.wait_group 1;" ::: "memory")

// ---------------------------------------------------------------------------
// Kernel 0: convert weights to f16 hi/lo
// ---------------------------------------------------------------------------
__global__ __launch_bounds__(256) void convw_kernel(
    const float* __restrict__ wq, const float* __restrict__ wk,
    const float* __restrict__ wv1, const float* __restrict__ wv2)
{
    int p = (blockIdx.x * 256 + threadIdx.x) * 2;
    float v0, v1;
    __half *dh, *dl;
    int off;
    if (p < 3 * EMB * DHEAD) {
        const float* src = (p < EMB * DHEAD) ? wq : (p < 2 * EMB * DHEAD) ? wk : wv1;
        int e = p & (EMB * DHEAD - 1);
        v0 = src[e]; v1 = src[e + 1];
        dh = g_Wh; dl = g_Wl; off = p;
    } else {
        int e = p - 3 * EMB * DHEAD;
        v0 = wv2[e]; v1 = wv2[e + 1];
        dh = g_W2h; dl = g_W2l; off = e;
    }
    uint32_t hi, lo;
    split2h(v0, v1, hi, lo);
    *reinterpret_cast<uint32_t*>(dh + off) = hi;
    *reinterpret_cast<uint32_t*>(dl + off) = lo;
}

// ---------------------------------------------------------------------------
// Kernel 1: fused projections. f16 split: hi pass f32-accum + cross f16-accum.
// 64-row tiles, 128 threads, 256 blocks, cp.async double-buffered weights.
// ---------------------------------------------------------------------------
#define PJ_XPITCH 80
#define PJ_WPITCH 144
#define PJ_XH 0
#define PJ_XL (64 * PJ_XPITCH)            // 5120
#define PJ_WBASE (2 * 64 * PJ_XPITCH)     // 10240
#define PJ_WTILE (32 * PJ_WPITCH)         // 4608
#define PJ_WSET (3 * PJ_WTILE)            // 13824
#define PJ_WBUF (2 * PJ_WSET)             // 27648
#define PJ_SMEM (PJ_WBASE + 2 * PJ_WBUF)  // 65536

__global__ __launch_bounds__(128) void proj_kernel(const float* __restrict__ x)
{
    extern __shared__ char sm[];
    const uint32_t sb = smem_u32(sm);
    const int tid = threadIdx.x, w = tid >> 5, lane = tid & 31;
    const int gr = lane >> 2, tig = lane & 3;
    const int m0 = blockIdx.x * 64;

    float acc[3][8][4];
#pragma unroll
    for (int t = 0; t < 3; t++)
#pragma unroll
        for (int j = 0; j < 8; j++)
#pragma unroll
            for (int q = 0; q < 4; q++) acc[t][j][q] = 0.f;

    const int mrow = w * 16 + (lane & 7) + ((lane >> 3) & 1) * 8;
    const int akb = (lane >> 4) * 16;
    const int krow = (lane >> 4) * 16 + ((lane >> 3) & 1) * 8 + (lane & 7);

    auto wload = [&](int k0, uint32_t bufbase) {
#pragma unroll
        for (int i = tid; i < 768; i += 128) {
            int t = i >> 8, r = (i >> 3) & 31, c = i & 7;
            size_t gi = (size_t)t * EMB * 64 + (size_t)(k0 + r) * 64 + c * 8;
            uint32_t d = bufbase + t * PJ_WTILE + r * PJ_WPITCH + c * 16;
            cp16(sb + d, g_Wh + gi);
            cp16(sb + d + PJ_WSET, g_Wl + gi);
        }
    };

    float4 xv[4], xn[4];
#pragma unroll
    for (int j = 0; j < 4; j++) {
        int i = tid + j * 128, r = i >> 3, c = (i & 7) * 4;
        xv[j] = *reinterpret_cast<const float4*>(&x[(size_t)(m0 + r) * EMB + c]);
    }
    wload(0, PJ_WBASE);
    CP_COMMIT();

    for (int it = 0; it < 32; it++) {
        const int k0 = it * 32;
        const uint32_t wb = PJ_WBASE + (uint32_t)(it & 1) * PJ_WBUF;
        if (it < 31) wload(k0 + 32, PJ_WBASE + (uint32_t)((it + 1) & 1) * PJ_WBUF);
        CP_COMMIT();
        if (it < 31) {
#pragma unroll
            for (int j = 0; j < 4; j++) {
                int i = tid + j * 128, r = i >> 3, c = (i & 7) * 4;
                xn[j] = *reinterpret_cast<const float4*>(&x[(size_t)(m0 + r) * EMB + k0 + 32 + c]);
            }
        }
#pragma unroll
        for (int j = 0; j < 4; j++) {
            int i = tid + j * 128, r = i >> 3, c = (i & 7) * 4;
            uint32_t h0, l0, h1, l1;
            split2h(xv[j].x, xv[j].y, h0, l0);
            split2h(xv[j].z, xv[j].w, h1, l1);
            uint32_t* ph = reinterpret_cast<uint32_t*>(sm + PJ_XH + r * PJ_XPITCH + c * 2);
            ph[0] = h0; ph[1] = h1;
            uint32_t* pl = reinterpret_cast<uint32_t*>(sm + PJ_XL + r * PJ_XPITCH + c * 2);
            pl[0] = l0; pl[1] = l1;
        }
        CP_WAIT1();
        __syncthreads();

        uint32_t ah[2][4], al[2][4];
#pragma unroll
        for (int kk = 0; kk < 2; kk++) {
            ldsm4(ah[kk], sb + PJ_XH + mrow * PJ_XPITCH + kk * 32 + akb);
            ldsm4(al[kk], sb + PJ_XL + mrow * PJ_XPITCH + kk * 32 + akb);
        }
#pragma unroll
        for (int t = 0; t < 3; t++) {
#pragma unroll
            for (int j = 0; j < 8; j++) {
                uint32_t bh[4], bl[4];
                ldsm4t(bh, sb + wb + t * PJ_WTILE + krow * PJ_WPITCH + j * 16);
                ldsm4t(bl, sb + wb + PJ_WSET + t * PJ_WTILE + krow * PJ_WPITCH + j * 16);
                float* c = acc[t][j];
                mma_f16f32(c, ah[0], bh[0], bh[1]);
                mma_f16f32(c, ah[1], bh[2], bh[3]);
                uint32_t c16[2] = {0u, 0u};
                mma_f16f16(c16, ah[0], bl[0], bl[1]);
                mma_f16f16(c16, ah[1], bl[2], bl[3]);
                mma_f16f16(c16, al[0], bh[0], bh[1]);
                mma_f16f16(c16, al[1], bh[2], bh[3]);
                float2 e0 = h2f2(c16[0]), e1 = h2f2(c16[1]);
                c[0] += INV_LOSCALE * e0.x; c[1] += INV_LOSCALE * e0.y;
                c[2] += INV_LOSCALE * e1.x; c[3] += INV_LOSCALE * e1.y;
            }
        }
        __syncthreads();
#pragma unroll
        for (int j = 0; j < 4; j++) xv[j] = xn[j];
    }

    // epilogue: Q,K -> f16 split (Q scaled); U -> bf16 split (PV stays bf16)
#pragma unroll
    for (int t = 0; t < 3; t++) {
        const float scl = (t == 0) ? 0.18033688f : 1.0f;  // 0.125 * log2(e)
#pragma unroll
        for (int j = 0; j < 8; j++) {
            int col = j * 8 + tig * 2;
            size_t r0 = (size_t)(m0 + w * 16 + gr);
            uint32_t h, l;
            if (t < 2) {
                __half* dh = (t == 0) ? g_Qh : g_Kh;
                __half* dl = (t == 0) ? g_Ql : g_Kl;
                split2h(acc[t][j][0] * scl, acc[t][j][1] * scl, h, l);
                *reinterpret_cast<uint32_t*>(dh + r0 * 64 + col) = h;
                *reinterpret_cast<uint32_t*>(dl + r0 * 64 + col) = l;
                split2h(acc[t][j][2] * scl, acc[t][j][3] * scl, h, l);
                *reinterpret_cast<uint32_t*>(dh + (r0 + 8) * 64 + col) = h;
                *reinterpret_cast<uint32_t*>(dl + (r0 + 8) * 64 + col) = l;
            } else {
                split2(acc[t][j][0], acc[t][j][1], h, l);
                *reinterpret_cast<uint32_t*>(g_Uh + r0 * 64 + col) = h;
                *reinterpret_cast<uint32_t*>(g_Ul + r0 * 64 + col) = l;
                split2(acc[t][j][2], acc[t][j][3], h, l);
                *reinterpret_cast<uint32_t*>(g_Uh + (r0 + 8) * 64 + col) = h;
                *reinterpret_cast<uint32_t*>(g_Ul + (r0 + 8) * 64 + col) = l;
            }
        }
    }
}

// ---------------------------------------------------------------------------
// Kernel 2: FA2 flash attention (R6 structure). Q/K f16 split (S: hi f32 +
// cross f16-accum); P/U bf16 3-pass. grid (SEQ/64, BATCH, 4); 128 threads.
// ---------------------------------------------------------------------------
#define FL_PITCH 144
#define FL_TILE (64 * FL_PITCH)       // 9216
#define FL_STAGE (4 * FL_TILE)        // 36864 (KH,KL,UH,UL)
#define FL_SMEM (2 * FL_STAGE)        // 73728

__global__ __launch_bounds__(128) void flash_kernel()
{
    extern __shared__ char sm[];
    const uint32_t sb = smem_u32(sm);
    const int tid = threadIdx.x, w = tid >> 5, lane = tid & 31;
    const int gr = lane >> 2, tig = lane & 3;
    const int qt = blockIdx.x, b = blockIdx.y, par = blockIdx.z;
    const int q0 = qt * 64;
    const size_t base = (size_t)b * SEQ;

    float* Op = g_Op[par];
    float* lp = g_l[par];
    const size_t r0s = base + q0 + w * 16 + gr;

    if (par > qt) {
        if (tig == 0) { lp[r0s] = 0.f; lp[r0s + 8] = 0.f; }
        float2 z = make_float2(0.f, 0.f);
#pragma unroll
        for (int j = 0; j < 8; j++) {
            int col = j * 8 + tig * 2;
            *reinterpret_cast<float2*>(&Op[r0s * 64 + col]) = z;
            *reinterpret_cast<float2*>(&Op[(r0s + 8) * 64 + col]) = z;
        }
        return;
    }

    // stage Q (64x64 hi/lo) into stage0, pull fragments
    for (int i = tid; i < 64 * 8; i += 128) {
        int r = i >> 3, c = i & 7;
        size_t gq = (base + q0 + r) * 64 + c * 8;
        *reinterpret_cast<uint4*>(sm + r * FL_PITCH + c * 16) =
            *reinterpret_cast<const uint4*>(g_Qh + gq);
        *reinterpret_cast<uint4*>(sm + FL_TILE + r * FL_PITCH + c * 16) =
            *reinterpret_cast<const uint4*>(g_Ql + gq);
    }
    __syncthreads();
    uint32_t qh[4][4], ql[4][4];
    {
        const int mrow = w * 16 + (lane & 7) + ((lane >> 3) & 1) * 8;
        const int akb = (lane >> 4) * 16;
#pragma unroll
        for (int kk = 0; kk < 4; kk++) {
            ldsm4(qh[kk], sb + mrow * FL_PITCH + kk * 32 + akb);
            ldsm4(ql[kk], sb + FL_TILE + mrow * FL_PITCH + kk * 32 + akb);
        }
    }
    __syncthreads();

    auto load_tile = [&](int kt, uint32_t bb) {
        const int k0 = kt * 64;
#pragma unroll
        for (int i = tid; i < 64 * 8; i += 128) {
            int r = i >> 3, c = i & 7;
            uint32_t d = bb + r * FL_PITCH + c * 16;
            size_t gk = (base + k0 + r) * 64 + c * 8;
            cp16(sb + d, g_Kh + gk);
            cp16(sb + d + FL_TILE, g_Kl + gk);
            cp16(sb + d + 2 * FL_TILE, g_Uh + gk);
            cp16(sb + d + 3 * FL_TILE, g_Ul + gk);
        }
    };

    float o[8][4];
#pragma unroll
    for (int j = 0; j < 8; j++)
#pragma unroll
        for (int q = 0; q < 4; q++) o[j][q] = 0.f;
    float l0 = 0.f, l1 = 0.f;

    const int row0 = q0 + w * 16 + gr, row1 = row0 + 8;

    load_tile(par, 0);
    CP_COMMIT();

    int it = 0;
    for (int kt = par; kt <= qt; kt += NSPLIT, it++) {
        const int k0 = kt * 64;
        const uint32_t bb = (uint32_t)(it & 1) * FL_STAGE;
        if (kt + NSPLIT <= qt) load_tile(kt + NSPLIT, (uint32_t)((it + 1) & 1) * FL_STAGE);
        CP_COMMIT();
        CP_WAIT1();
        __syncthreads();

        // S = Q K^T : hi pass f32-accum + scaled cross passes f16-accum
        float s[8][4];
#pragma unroll
        for (int j = 0; j < 8; j++) {
#pragma unroll
            for (int q = 0; q < 4; q++) s[j][q] = 0.f;
            uint32_t a0 = sb + bb + (j * 8 + (lane & 7)) * FL_PITCH + (lane >> 3) * 16;
            uint32_t a1 = a0 + FL_TILE;
            uint32_t bh[4], bh2[4], bl[4], bl2[4];
            ldsm4(bh, a0); ldsm4(bh2, a0 + 64);
            ldsm4(bl, a1); ldsm4(bl2, a1 + 64);
            float* c = s[j];
            mma_f16f32(c, qh[0], bh[0], bh[1]);
            mma_f16f32(c, qh[1], bh[2], bh[3]);
            mma_f16f32(c, qh[2], bh2[0], bh2[1]);
            mma_f16f32(c, qh[3], bh2[2], bh2[3]);
            uint32_t s16[2] = {0u, 0u};
            mma_f16f16(s16, qh[0], bl[0], bl[1]);
            mma_f16f16(s16, qh[1], bl[2], bl[3]);
            mma_f16f16(s16, qh[2], bl2[0], bl2[1]);
            mma_f16f16(s16, qh[3], bl2[2], bl2[3]);
            mma_f16f16(s16, ql[0], bh[0], bh[1]);
            mma_f16f16(s16, ql[1], bh[2], bh[3]);
            mma_f16f16(s16, ql[2], bh2[0], bh2[1]);
            mma_f16f16(s16, ql[3], bh2[2], bh2[3]);
            float2 e0 = h2f2(s16[0]), e1 = h2f2(s16[1]);
            c[0] += INV_LOSCALE * e0.x; c[1] += INV_LOSCALE * e0.y;
            c[2] += INV_LOSCALE * e1.x; c[3] += INV_LOSCALE * e1.y;
        }

        // softmax: p = exp2(s); causal mask only on diagonal tile
        const bool diag = (kt == qt);
#pragma unroll
        for (int j = 0; j < 8; j++) {
            int cb = k0 + j * 8 + tig * 2;
            float p0 = ex2(s[j][0]), p1 = ex2(s[j][1]);
            float p2 = ex2(s[j][2]), p3 = ex2(s[j][3]);
            if (diag) {
                if (cb > row0) p0 = 0.f;
                if (cb + 1 > row0) p1 = 0.f;
                if (cb > row1) p2 = 0.f;
                if (cb + 1 > row1) p3 = 0.f;
            }
            s[j][0] = p0; s[j][1] = p1; s[j][2] = p2; s[j][3] = p3;
            l0 += p0 + p1;
            l1 += p2 + p3;
        }

        // P fragments (C-frag -> A-frag identity), bf16 hi/lo (range-safe)
        uint32_t ph[4][4], pl[4][4];
#pragma unroll
        for (int kk = 0; kk < 4; kk++) {
            split2(s[2 * kk][0], s[2 * kk][1], ph[kk][0], pl[kk][0]);
            split2(s[2 * kk][2], s[2 * kk][3], ph[kk][1], pl[kk][1]);
            split2(s[2 * kk + 1][0], s[2 * kk + 1][1], ph[kk][2], pl[kk][2]);
            split2(s[2 * kk + 1][2], s[2 * kk + 1][3], ph[kk][3], pl[kk][3]);
        }

        // O += P U (bf16 split, 3 passes)
#pragma unroll
        for (int jp = 0; jp < 4; jp++) {
#pragma unroll
            for (int kk = 0; kk < 4; kk++) {
                int krow = kk * 16 + ((lane >> 3) & 1) * 8 + (lane & 7);
                int nbyte = (jp * 2 + (lane >> 4)) * 16;
                uint32_t bh[4], bl[4];
                ldsm4t(bh, sb + bb + 2 * FL_TILE + krow * FL_PITCH + nbyte);
                ldsm4t(bl, sb + bb + 3 * FL_TILE + krow * FL_PITCH + nbyte);
                mma_bf16(o[2 * jp], ph[kk], bh[0], bh[1]);
                mma_bf16(o[2 * jp + 1], ph[kk], bh[2], bh[3]);
                mma_bf16(o[2 * jp], ph[kk], bl[0], bl[1]);
                mma_bf16(o[2 * jp + 1], ph[kk], bl[2], bl[3]);
                mma_bf16(o[2 * jp], pl[kk], bh[0], bh[1]);
                mma_bf16(o[2 * jp + 1], pl[kk], bh[2], bh[3]);
            }
        }
        __syncthreads();
    }

    l0 += __shfl_xor_sync(0xffffffffu, l0, 1);
    l0 += __shfl_xor_sync(0xffffffffu, l0, 2);
    l1 += __shfl_xor_sync(0xffffffffu, l1, 1);
    l1 += __shfl_xor_sync(0xffffffffu, l1, 2);

    if (tig == 0) { lp[r0s] = l0; lp[r0s + 8] = l1; }
#pragma unroll
    for (int j = 0; j < 8; j++) {
        int col = j * 8 + tig * 2;
        *reinterpret_cast<float2*>(&Op[r0s * 64 + col]) = make_float2(o[j][0], o[j][1]);
        *reinterpret_cast<float2*>(&Op[(r0s + 8) * 64 + col]) = make_float2(o[j][2], o[j][3]);
    }
}

// ---------------------------------------------------------------------------
// Kernel 2b: combine split-KV partials, normalize, emit f16 hi/lo.
// ---------------------------------------------------------------------------
__global__ __launch_bounds__(256) void combine_kernel()
{
    int i = (blockIdx.x * 256 + threadIdx.x) * 4;
    int row = i >> 6;
    float lsum = g_l[0][row] + g_l[1][row] + g_l[2][row] + g_l[3][row];
    float inv = 1.0f / lsum;
    float4 a = *reinterpret_cast<const float4*>(&g_Op[0][i]);
    float4 b = *reinterpret_cast<const float4*>(&g_Op[1][i]);
    float4 c = *reinterpret_cast<const float4*>(&g_Op[2][i]);
    float4 d = *reinterpret_cast<const float4*>(&g_Op[3][i]);
    float v0 = (a.x + b.x + c.x + d.x) * inv;
    float v1 = (a.y + b.y + c.y + d.y) * inv;
    float v2 = (a.z + b.z + c.z + d.z) * inv;
    float v3 = (a.w + b.w + c.w + d.w) * inv;
    uint32_t h0, l0, h1, l1;
    split2h(v0, v1, h0, l0);
    split2h(v2, v3, h1, l1);
    *reinterpret_cast<uint2*>(g_Oh + i) = make_uint2(h0, h1);
    *reinterpret_cast<uint2*>(g_Ol + i) = make_uint2(l0, l1);
}

// ---------------------------------------------------------------------------
// Kernel 3: out[256x256 tile] = O64 @ w_v2 (f16 split, cross f16-accum).
// A staged once; W in two 128-col halves. grid (4, 64), 256 threads.
// ---------------------------------------------------------------------------
#define OP_OPITCH 144
#define OP_WPITCH 272
#define OP_AH 0
#define OP_AL (256 * OP_OPITCH)            // 36864
#define OP_WH (2 * 256 * OP_OPITCH)        // 73728
#define OP_WL (OP_WH + 64 * OP_WPITCH)     // 91136
#define OP_SMEM (OP_WL + 64 * OP_WPITCH)   // 108544

__global__ __launch_bounds__(256) void outproj_kernel(float* __restrict__ out)
{
    extern __shared__ char sm[];
    const uint32_t sb = smem_u32(sm);
    const int tid = threadIdx.x, w = tid >> 5, lane = tid & 31;
    const int gr = lane >> 2, tig = lane & 3;
    const int row0 = blockIdx.y * 256, cbase = blockIdx.x * 256;

    for (int i = tid; i < 256 * 8; i += 256) {
        int r = i >> 3, c = i & 7;
        size_t gi = (size_t)(row0 + r) * 64 + c * 8;
        *reinterpret_cast<uint4*>(sm + OP_AH + r * OP_OPITCH + c * 16) =
            *reinterpret_cast<const uint4*>(g_Oh + gi);
        *reinterpret_cast<uint4*>(sm + OP_AL + r * OP_OPITCH + c * 16) =
            *reinterpret_cast<const uint4*>(g_Ol + gi);
    }
    for (int i = tid; i < 64 * 16; i += 256) {
        int r = i >> 4, c = i & 15;
        size_t gi = (size_t)r * EMB + cbase + c * 8;
        *reinterpret_cast<uint4*>(sm + OP_WH + r * OP_WPITCH + c * 16) =
            *reinterpret_cast<const uint4*>(g_W2h + gi);
        *reinterpret_cast<uint4*>(sm + OP_WL + r * OP_WPITCH + c * 16) =
            *reinterpret_cast<const uint4*>(g_W2l + gi);
    }
    __syncthreads();

    uint32_t ah[2][4][4], al[2][4][4];
    const int akb = (lane >> 4) * 16;
#pragma unroll
    for (int m = 0; m < 2; m++) {
        const int mrow = w * 32 + m * 16 + (lane & 7) + ((lane >> 3) & 1) * 8;
#pragma unroll
        for (int kk = 0; kk < 4; kk++) {
            ldsm4(ah[m][kk], sb + OP_AH + mrow * OP_OPITCH + kk * 32 + akb);
            ldsm4(al[m][kk], sb + OP_AL + mrow * OP_OPITCH + kk * 32 + akb);
        }
    }

#pragma unroll
    for (int h = 0; h < 2; h++) {
        if (h == 1) {
            __syncthreads();
            for (int i = tid; i < 64 * 16; i += 256) {
                int r = i >> 4, c = i & 15;
                size_t gi = (size_t)r * EMB + cbase + 128 + c * 8;
                *reinterpret_cast<uint4*>(sm + OP_WH + r * OP_WPITCH + c * 16) =
                    *reinterpret_cast<const uint4*>(g_W2h + gi);
                *reinterpret_cast<uint4*>(sm + OP_WL + r * OP_WPITCH + c * 16) =
                    *reinterpret_cast<const uint4*>(g_W2l + gi);
            }
            __syncthreads();
        }
        const int col0 = cbase + h * 128;
#pragma unroll
        for (int j = 0; j < 16; j++) {
            float c[2][4];
            uint32_t c16[2][2];
#pragma unroll
            for (int m = 0; m < 2; m++) {
#pragma unroll
                for (int q = 0; q < 4; q++) c[m][q] = 0.f;
                c16[m][0] = 0u; c16[m][1] = 0u;
            }
#pragma unroll
            for (int kp = 0; kp < 2; kp++) {
                int krow = kp * 32 + (lane >> 4) * 16 + ((lane >> 3) & 1) * 8 + (lane & 7);
                uint32_t bh[4], bl[4];
                ldsm4t(bh, sb + OP_WH + krow * OP_WPITCH + j * 16);
                ldsm4t(bl, sb + OP_WL + krow * OP_WPITCH + j * 16);
#pragma unroll
                for (int m = 0; m < 2; m++) {
                    mma_f16f32(c[m], ah[m][2 * kp], bh[0], bh[1]);
                    mma_f16f32(c[m], ah[m][2 * kp + 1], bh[2], bh[3]);
                    mma_f16f16(c16[m], ah[m][2 * kp], bl[0], bl[1]);
                    mma_f16f16(c16[m], ah[m][2 * kp + 1], bl[2], bl[3]);
                    mma_f16f16(c16[m], al[m][2 * kp], bh[0], bh[1]);
                    mma_f16f16(c16[m], al[m][2 * kp + 1], bh[2], bh[3]);
                }
            }
            int col = col0 + j * 8 + tig * 2;
#pragma unroll
            for (int m = 0; m < 2; m++) {
                float2 e0 = h2f2(c16[m][0]), e1 = h2f2(c16[m][1]);
                int r = row0 + w * 32 + m * 16 + gr;
                *reinterpret_cast<float2*>(&out[(size_t)r * EMB + col]) =
                    make_float2(c[m][0] + INV_LOSCALE * e0.x,
                                c[m][1] + INV_LOSCALE * e0.y);
                *reinterpret_cast<float2*>(&out[(size_t)(r + 8) * EMB + col]) =
                    make_float2(c[m][2] + INV_LOSCALE * e1.x,
                                c[m][3] + INV_LOSCALE * e1.y);
            }
        }
    }
}

// ---------------------------------------------------------------------------
extern "C" void kernel_launch(void* const* d_in, const int* in_sizes, int n_in,
                              void* d_out, int out_size)
{
    const float* x    = (const float*)d_in[0];
    const float* w_q  = (const float*)d_in[1];
    const float* w_k  = (const float*)d_in[2];
    const float* w_v1 = (const float*)d_in[3];
    const float* w_v2 = (const float*)d_in[4];
    float* out = (float*)d_out;
    (void)in_sizes; (void)n_in; (void)out_size;

    cudaFuncSetAttribute(proj_kernel, cudaFuncAttributeMaxDynamicSharedMemorySize, PJ_SMEM);
    cudaFuncSetAttribute(flash_kernel, cudaFuncAttributeMaxDynamicSharedMemorySize, FL_SMEM);
    cudaFuncSetAttribute(outproj_kernel, cudaFuncAttributeMaxDynamicSharedMemorySize, OP_SMEM);

    convw_kernel<<<512, 256>>>(w_q, w_k, w_v1, w_v2);
    proj_kernel<<<MTOT / 64, 128, PJ_SMEM>>>(x);
    flash_kernel<<<dim3(SEQ / 64, BATCH, NSPLIT), 128, FL_SMEM>>>();
    combine_kernel<<<MTOT * DHEAD / 1024, 256>>>();
    outproj_kernel<<<dim3(EMB / 256, MTOT / 256), 256, OP_SMEM>>>(out);
}